// round 7
// baseline (speedup 1.0000x reference)
#include <cuda_runtime.h>
#include <math.h>

// Problem constants
#define NN   256
#define CC   512
#define TT   4
#define HH   8
#define WWID 8
#define HWSZ 64          // HH*WWID
#define PP   256         // TT*HWSZ

typedef unsigned long long ull;

// ---------------------------------------------------------------------------
// Scratch (device globals — no allocation allowed).
// Layout for q/k/v/virt is position-major: [p][n][c], p = t*64 + h*8 + w.
// ---------------------------------------------------------------------------
__device__ __align__(16) float g_q[PP * NN * CC];
__device__ __align__(16) float g_k[PP * NN * CC];
__device__ __align__(16) float g_v[PP * NN * CC];
__device__ __align__(16) float g_virt[PP * NN * CC];
__device__ __align__(16) float g_att[PP * NN * NN];
__device__ float g_mu[NN];
__device__ float g_rs[NN];

// ---------------------------------------------------------------------------
// Packed f32x2 helpers (Blackwell FFMA2 path)
// ---------------------------------------------------------------------------
__device__ __forceinline__ ull pack2(float v) {
    ull r;
    asm("mov.b64 %0, {%1, %1};" : "=l"(r) : "f"(v));
    return r;
}
__device__ __forceinline__ ull fma2(ull a, ull b, ull c) {
    ull d;
    asm("fma.rn.f32x2 %0, %1, %2, %3;" : "=l"(d) : "l"(a), "l"(b), "l"(c));
    return d;
}
__device__ __forceinline__ void unpack2(ull a, float& lo, float& hi) {
    asm("mov.b64 {%0, %1}, %2;" : "=f"(lo), "=f"(hi) : "l"(a));
}

// ---------------------------------------------------------------------------
// K1: q,k,v = conv1x3x3(x, Wq/Wk/Wv).  One block = one (n,t) slice × 64 co.
// Thread map: lane -> co pair (2 channels, packed f32x2), warp -> h row,
// each thread covers all 8 w positions. x tile staged with halo in smem.
// Writes q/k/v in [p][n][c] layout (coalesced 256B per warp).
// ---------------------------------------------------------------------------
__global__ __launch_bounds__(256) void conv_qkv_kernel(
    const float* __restrict__ x,
    const float* __restrict__ Wq,
    const float* __restrict__ Wk,
    const float* __restrict__ Wv)
{
    __shared__ __align__(16) float ws[3 * 4 * 9 * 64];  // [conv][ci][s][co]  27.6 KB
    __shared__ __align__(16) float xs[4 * 10 * 10];     // [ci][h+halo][w+halo]

    const int co_base = blockIdx.x * 64;
    const int nt = blockIdx.y;
    const int n = nt >> 2, t = nt & 3;
    const int tid = threadIdx.x;
    const int l = tid & 31, wp = tid >> 5;   // wp = output h row

    ull acc[3][8];
#pragma unroll
    for (int c = 0; c < 3; c++)
#pragma unroll
        for (int i = 0; i < 8; i++) acc[c][i] = 0ULL;

    for (int kb = 0; kb < 128; kb++) {
        const int ci0 = kb * 4;
        // stage weights: [conv][ci][s][co]
        for (int idx = tid; idx < 6912; idx += 256) {
            int conv = idx / 2304; int r = idx - conv * 2304;
            int co = r / 36;       int r2 = r - co * 36;
            int ci = r2 / 9;       int s = r2 - ci * 9;
            const float* Wsrc = (conv == 0) ? Wq : ((conv == 1) ? Wk : Wv);
            ws[((conv * 4 + ci) * 9 + s) * 64 + co] =
                Wsrc[((co_base + co) * CC + ci0 + ci) * 9 + s];
        }
        // stage x tile with zero halo (padding (1,1) in h,w)
        for (int idx = tid; idx < 400; idx += 256) {
            int ci = idx / 100; int r = idx - ci * 100;
            int hh = r / 10;    int wwv = r - hh * 10;
            int hs = hh - 1, wsv = wwv - 1;
            float v = 0.0f;
            if ((unsigned)hs < 8u && (unsigned)wsv < 8u)
                v = x[((n * CC + ci0 + ci) * TT + t) * HWSZ + hs * 8 + wsv];
            xs[idx] = v;
        }
        __syncthreads();
#pragma unroll
        for (int ci = 0; ci < 4; ci++) {
#pragma unroll
            for (int dh = 0; dh < 3; dh++) {
                const float* row = &xs[(ci * 10 + wp + dh) * 10];
                ull xr2[10];
#pragma unroll
                for (int j = 0; j < 10; j++) xr2[j] = pack2(row[j]);
#pragma unroll
                for (int dw = 0; dw < 3; dw++) {
                    const int s = dh * 3 + dw;
#pragma unroll
                    for (int cv = 0; cv < 3; cv++) {
                        ull w2 = *(const ull*)&ws[((cv * 4 + ci) * 9 + s) * 64 + 2 * l];
#pragma unroll
                        for (int i = 0; i < 8; i++)
                            acc[cv][i] = fma2(w2, xr2[i + dw], acc[cv][i]);
                    }
                }
            }
        }
        __syncthreads();
    }
#pragma unroll
    for (int i = 0; i < 8; i++) {
        const int p = t * HWSZ + wp * 8 + i;
        const int off = (p * NN + n) * CC + co_base + 2 * l;
        *(ull*)&g_q[off] = acc[0][i];
        *(ull*)&g_k[off] = acc[1][i];
        *(ull*)&g_v[off] = acc[2][i];
    }
}

// ---------------------------------------------------------------------------
// K2: per-position scores  S_p = (Q_p K_p^T) * 1/sqrt(C).
// Block = 64 i-rows × 128 j-cols of one p.  Lane -> j pairs, warp -> i rows.
// ---------------------------------------------------------------------------
__global__ __launch_bounds__(256) void scores_kernel()
{
    __shared__ __align__(16) float qs[16 * 64];    // [kk][i]
    __shared__ __align__(16) float ks[16 * 128];   // [kk][j]
    const int p = blockIdx.y;
    const int jt = blockIdx.x & 1, it = blockIdx.x >> 1;
    const int tid = threadIdx.x, l = tid & 31, wp = tid >> 5;

    ull acc[8][2];
#pragma unroll
    for (int r = 0; r < 8; r++) { acc[r][0] = 0ULL; acc[r][1] = 0ULL; }

    for (int c0 = 0; c0 < CC; c0 += 16) {
        for (int idx = tid; idx < 1024; idx += 256) {
            int i_loc = idx >> 4, kk = idx & 15;
            qs[kk * 64 + i_loc] = g_q[(p * NN + it * 64 + i_loc) * CC + c0 + kk];
        }
        for (int idx = tid; idx < 2048; idx += 256) {
            int j_loc = idx >> 4, kk = idx & 15;
            ks[kk * 128 + j_loc] = g_k[(p * NN + jt * 128 + j_loc) * CC + c0 + kk];
        }
        __syncthreads();
#pragma unroll
        for (int kk = 0; kk < 16; kk++) {
            ull kA = *(const ull*)&ks[kk * 128 + 2 * l];
            ull kB = *(const ull*)&ks[kk * 128 + 64 + 2 * l];
#pragma unroll
            for (int r = 0; r < 8; r++) {
                ull qb = pack2(qs[kk * 64 + wp * 8 + r]);
                acc[r][0] = fma2(qb, kA, acc[r][0]);
                acc[r][1] = fma2(qb, kB, acc[r][1]);
            }
        }
        __syncthreads();
    }
    const float scale = rsqrtf((float)CC);
#pragma unroll
    for (int r = 0; r < 8; r++) {
#pragma unroll
        for (int hf = 0; hf < 2; hf++) {
            float lo, hi;
            unpack2(acc[r][hf], lo, hi);
            const int i = it * 64 + wp * 8 + r;
            const int j = jt * 128 + hf * 64 + 2 * l;
            float2 val; val.x = lo * scale; val.y = hi * scale;
            *(float2*)&g_att[(p * NN + i) * NN + j] = val;
        }
    }
}

// ---------------------------------------------------------------------------
// K3: masked softmax over j (group mask from roi_inds).  Warp = one (p,i) row.
// Invalid entries -> exp underflows to exactly 0, so K4 is a dense GEMM.
// ---------------------------------------------------------------------------
__global__ __launch_bounds__(256) void softmax_kernel(const int* __restrict__ roi)
{
    __shared__ int rg[256];
    const int tid = threadIdx.x, l = tid & 31, wp = tid >> 5;
    rg[tid] = roi[tid];
    __syncthreads();
    const int row = blockIdx.x * 8 + wp;
    const int p = row >> 8, i = row & 255;
    const int gi = rg[i];
    float* rowp = &g_att[(p * NN + i) * NN];

    float v[8];
#pragma unroll
    for (int jj = 0; jj < 8; jj++) {
        int j = jj * 32 + l;
        float s = rowp[j];
        v[jj] = (rg[j] == gi) ? s : -1e30f;
    }
    float m = v[0];
#pragma unroll
    for (int jj = 1; jj < 8; jj++) m = fmaxf(m, v[jj]);
#pragma unroll
    for (int off = 16; off; off >>= 1) m = fmaxf(m, __shfl_xor_sync(0xffffffffu, m, off));

    float e[8]; float sum = 0.0f;
#pragma unroll
    for (int jj = 0; jj < 8; jj++) { e[jj] = expf(v[jj] - m); sum += e[jj]; }
#pragma unroll
    for (int off = 16; off; off >>= 1) sum += __shfl_xor_sync(0xffffffffu, sum, off);
    const float inv = 1.0f / sum;
#pragma unroll
    for (int jj = 0; jj < 8; jj++) rowp[jj * 32 + l] = e[jj] * inv;
}

// ---------------------------------------------------------------------------
// K4: virt_p = att_p · V_p.  Block = 64 i-rows × 128 c-cols of one p.
// ---------------------------------------------------------------------------
__global__ __launch_bounds__(256) void virt_kernel()
{
    __shared__ __align__(16) float as_[16 * 64];   // [jj][i]
    __shared__ __align__(16) float vs_[16 * 128];  // [jj][c]
    const int p = blockIdx.y;
    const int ct = blockIdx.x & 3, it = blockIdx.x >> 2;
    const int tid = threadIdx.x, l = tid & 31, wp = tid >> 5;

    ull acc[8][2];
#pragma unroll
    for (int r = 0; r < 8; r++) { acc[r][0] = 0ULL; acc[r][1] = 0ULL; }

    for (int j0 = 0; j0 < NN; j0 += 16) {
        for (int idx = tid; idx < 1024; idx += 256) {
            int i_loc = idx >> 4, jj = idx & 15;
            as_[jj * 64 + i_loc] = g_att[(p * NN + it * 64 + i_loc) * NN + j0 + jj];
        }
        for (int idx = tid; idx < 2048; idx += 256) {
            int jj = idx >> 7, cl = idx & 127;
            vs_[jj * 128 + cl] = g_v[(p * NN + j0 + jj) * CC + ct * 128 + cl];
        }
        __syncthreads();
#pragma unroll
        for (int jj = 0; jj < 16; jj++) {
            ull vA = *(const ull*)&vs_[jj * 128 + 2 * l];
            ull vB = *(const ull*)&vs_[jj * 128 + 64 + 2 * l];
#pragma unroll
            for (int r = 0; r < 8; r++) {
                ull ab = pack2(as_[jj * 64 + wp * 8 + r]);
                acc[r][0] = fma2(ab, vA, acc[r][0]);
                acc[r][1] = fma2(ab, vB, acc[r][1]);
            }
        }
        __syncthreads();
    }
#pragma unroll
    for (int r = 0; r < 8; r++) {
        const int i = it * 64 + wp * 8 + r;
#pragma unroll
        for (int hf = 0; hf < 2; hf++) {
            const int c = ct * 128 + hf * 64 + 2 * l;
            *(ull*)&g_virt[(p * NN + i) * CC + c] = acc[r][hf];
        }
    }
}

// ---------------------------------------------------------------------------
// K5: GroupNorm(num_groups=1) stats per sample n: mean/var over (C,T,H,W).
// ---------------------------------------------------------------------------
__global__ __launch_bounds__(256) void stats_kernel()
{
    __shared__ float r1[256];
    __shared__ float r2[256];
    const int n = blockIdx.x;
    const int tid = threadIdx.x;
    float s = 0.0f, s2 = 0.0f;
    for (int e = tid; e < PP * CC; e += 256) {
        int p = e >> 9, c = e & 511;
        float v = g_virt[(p * NN + n) * CC + c];
        s += v; s2 += v * v;
    }
    r1[tid] = s; r2[tid] = s2;
    __syncthreads();
    for (int off = 128; off; off >>= 1) {
        if (tid < off) { r1[tid] += r1[tid + off]; r2[tid] += r2[tid + off]; }
        __syncthreads();
    }
    if (tid == 0) {
        const float invN = 1.0f / (float)(PP * CC);
        float mu = r1[0] * invN;
        float var = r2[0] * invN - mu * mu;
        g_mu[n] = mu;
        g_rs[n] = rsqrtf(var + 1e-5f);
    }
}

// ---------------------------------------------------------------------------
// K7: out = x + conv1x3x3( relu(GN(virt)), Wc ).
// Normalization + relu fused into the smem tile load (zero halo applied AFTER
// the nonlinearity, matching the reference's conv padding of the activated map).
// ---------------------------------------------------------------------------
__global__ __launch_bounds__(256) void conv_out_kernel(
    const float* __restrict__ x,
    const float* __restrict__ Wc,
    const float* __restrict__ gamma,
    const float* __restrict__ beta,
    float* __restrict__ out)
{
    __shared__ __align__(16) float ws[16 * 9 * 64];   // [ci][s][co] 36.9 KB
    __shared__ __align__(16) float xs[16 * 10 * 10];  // 6.4 KB

    const int co_base = blockIdx.x * 64;
    const int nt = blockIdx.y;
    const int n = nt >> 2, t = nt & 3;
    const int tid = threadIdx.x, l = tid & 31, wp = tid >> 5;
    const float mu = g_mu[n], rs = g_rs[n];

    ull acc[8];
#pragma unroll
    for (int i = 0; i < 8; i++) acc[i] = 0ULL;

    for (int kb = 0; kb < 32; kb++) {
        const int ci0 = kb * 16;
        for (int idx = tid; idx < 9216; idx += 256) {
            int co = idx / 144; int r = idx - co * 144;
            int ci = r / 9;     int s = r - ci * 9;
            ws[(ci * 9 + s) * 64 + co] = Wc[((co_base + co) * CC + ci0 + ci) * 9 + s];
        }
        for (int idx = tid; idx < 1600; idx += 256) {
            int ci = idx / 100; int r = idx - ci * 100;
            int hh = r / 10;    int wwv = r - hh * 10;
            int hs = hh - 1, wsv = wwv - 1;
            float val = 0.0f;
            if ((unsigned)hs < 8u && (unsigned)wsv < 8u) {
                int c = ci0 + ci;
                float raw = g_virt[((t * HWSZ + hs * 8 + wsv) * NN + n) * CC + c];
                float ag = rs * gamma[c];
                val = fmaxf(fmaf(raw, ag, beta[c] - mu * ag), 0.0f);
            }
            xs[idx] = val;
        }
        __syncthreads();
#pragma unroll
        for (int ci = 0; ci < 16; ci++) {
#pragma unroll
            for (int dh = 0; dh < 3; dh++) {
                const float* row = &xs[(ci * 10 + wp + dh) * 10];
                ull xr2[10];
#pragma unroll
                for (int j = 0; j < 10; j++) xr2[j] = pack2(row[j]);
#pragma unroll
                for (int dw = 0; dw < 3; dw++) {
                    ull w2 = *(const ull*)&ws[(ci * 9 + dh * 3 + dw) * 64 + 2 * l];
#pragma unroll
                    for (int i = 0; i < 8; i++)
                        acc[i] = fma2(w2, xr2[i + dw], acc[i]);
                }
            }
        }
        __syncthreads();
    }
    // residual add + store in native [N][C][T][H][W] layout
#pragma unroll
    for (int i = 0; i < 8; i++) {
        float lo, hi;
        unpack2(acc[i], lo, hi);
        const int sp = wp * 8 + i;
        const int a0 = ((n * CC + co_base + 2 * l) * TT + t) * HWSZ + sp;
        const int a1 = a0 + TT * HWSZ;   // next channel
        out[a0] = x[a0] + lo;
        out[a1] = x[a1] + hi;
    }
}

// ---------------------------------------------------------------------------
// Launch
// ---------------------------------------------------------------------------
extern "C" void kernel_launch(void* const* d_in, const int* in_sizes, int n_in,
                              void* d_out, int out_size)
{
    const float* x     = (const float*)d_in[0];
    const int*   roi   = (const int*)d_in[1];
    const float* Wq    = (const float*)d_in[2];
    const float* Wk    = (const float*)d_in[3];
    const float* Wv    = (const float*)d_in[4];
    const float* Wc    = (const float*)d_in[5];
    const float* gamma = (const float*)d_in[6];
    const float* beta  = (const float*)d_in[7];
    float* out = (float*)d_out;

    conv_qkv_kernel<<<dim3(8, 1024), 256>>>(x, Wq, Wk, Wv);
    scores_kernel<<<dim3(8, 256), 256>>>();
    softmax_kernel<<<dim3(8192), 256>>>(roi);
    virt_kernel<<<dim3(16, 256), 256>>>();
    stats_kernel<<<dim3(256), 256>>>();
    conv_out_kernel<<<dim3(8, 1024), 256>>>(x, Wc, gamma, beta, out);
}

// round 9
// speedup vs baseline: 4.9617x; 4.9617x over previous
#include <cuda_runtime.h>
#include <cuda_bf16.h>
#include <math.h>

#define NN   256
#define CC   512
#define TT   4
#define HWSZ 64
#define PP   256
#define KTOT 4608
#define NCHUNK 72

typedef unsigned long long ull;

// ---------------- scratch (device globals; no allocation allowed) ----------
__device__ __align__(16) float g_q[PP * NN * CC];
__device__ __align__(16) float g_k[PP * NN * CC];
__device__ __align__(16) float g_v[PP * NN * CC];
__device__ __align__(16) float g_virt[PP * NN * CC];
__device__ __align__(16) float g_att[PP * NN * NN];
__device__ float g_mu[NN];
__device__ float g_rs[NN];
__device__ __align__(1024) __nv_bfloat16 g_wh[4 * CC * KTOT];   // [conv][co][k], k=s*512+ci
__device__ __align__(1024) __nv_bfloat16 g_wl[4 * CC * KTOT];
__device__ __align__(1024) __nv_bfloat16 g_xh[NN * PP * CC];    // [n][p][c]
__device__ __align__(1024) __nv_bfloat16 g_xl[NN * PP * CC];
__device__ __align__(1024) __nv_bfloat16 g_vbh[NN * PP * CC];
__device__ __align__(1024) __nv_bfloat16 g_vbl[NN * PP * CC];

// ---------------- plain-target PTX helpers (sm_80 level only) -------------
__device__ __forceinline__ unsigned smem_u32(const void* p) {
    unsigned a;
    asm("{ .reg .u64 t; cvta.to.shared.u64 t, %1; cvt.u32.u64 %0, t; }" : "=r"(a) : "l"(p));
    return a;
}
__device__ __forceinline__ void cp16(unsigned dst, const void* src, unsigned sz) {
    asm volatile("cp.async.cg.shared.global [%0], [%1], 16, %2;"
                 :: "r"(dst), "l"(src), "r"(sz) : "memory");
}
__device__ __forceinline__ void cp_commit() {
    asm volatile("cp.async.commit_group;" ::: "memory");
}
__device__ __forceinline__ void cp_wait1() {
    asm volatile("cp.async.wait_group 1;" ::: "memory");
}
__device__ __forceinline__ void cp_wait0() {
    asm volatile("cp.async.wait_group 0;" ::: "memory");
}
__device__ __forceinline__ void ldsm4(unsigned* r, unsigned a) {
    asm volatile("ldmatrix.sync.aligned.m8n8.x4.shared.b16 {%0,%1,%2,%3}, [%4];"
                 : "=r"(r[0]), "=r"(r[1]), "=r"(r[2]), "=r"(r[3]) : "r"(a));
}
__device__ __forceinline__ void mma16816(float* d, const unsigned* a, const unsigned* b) {
    asm volatile(
        "mma.sync.aligned.m16n8k16.row.col.f32.bf16.bf16.f32 "
        "{%0,%1,%2,%3}, {%4,%5,%6,%7}, {%8,%9}, {%0,%1,%2,%3};"
        : "+f"(d[0]), "+f"(d[1]), "+f"(d[2]), "+f"(d[3])
        : "r"(a[0]), "r"(a[1]), "r"(a[2]), "r"(a[3]), "r"(b[0]), "r"(b[1]));
}
__device__ __forceinline__ ull pack2(float v) { ull r; asm("mov.b64 %0, {%1, %1};" : "=l"(r) : "f"(v)); return r; }
__device__ __forceinline__ ull fma2(ull a, ull b, ull c) {
    ull d; asm("fma.rn.f32x2 %0, %1, %2, %3;" : "=l"(d) : "l"(a), "l"(b), "l"(c)); return d;
}
__device__ __forceinline__ void unpack2(ull a, float& lo, float& hi) {
    asm("mov.b64 {%0, %1}, %2;" : "=f"(lo), "=f"(hi) : "l"(a));
}

// ---------------- conversion kernels ----------------
__global__ __launch_bounds__(256) void split_w_kernel(
    const float* __restrict__ Wq, const float* __restrict__ Wk,
    const float* __restrict__ Wv, const float* __restrict__ Wc)
{
    int idx = blockIdx.x * 256 + threadIdx.x;
    int conv = idx / (CC * KTOT);
    int r = idx - conv * (CC * KTOT);
    int co = r / KTOT, k = r - co * KTOT;
    int s = k >> 9, ci = k & 511;
    const float* W = (conv == 0) ? Wq : (conv == 1) ? Wk : (conv == 2) ? Wv : Wc;
    float v = W[(co * CC + ci) * 9 + s];
    __nv_bfloat16 h = __float2bfloat16(v);
    g_wh[idx] = h;
    g_wl[idx] = __float2bfloat16(v - __bfloat162float(h));
}

// x [n][c][p] -> bf16 hi/lo [n][p][c]
__global__ __launch_bounds__(256) void split_x_kernel(const float* __restrict__ x)
{
    __shared__ float ts[64][65];
    const int n = blockIdx.z, c0 = blockIdx.y * 64, p0 = blockIdx.x * 64;
    const int tid = threadIdx.x;
    for (int e = tid; e < 4096; e += 256) {
        int i = e >> 6, j = e & 63;
        ts[i][j] = x[(n * CC + c0 + i) * PP + p0 + j];
    }
    __syncthreads();
    for (int e = tid; e < 4096; e += 256) {
        int i = e >> 6, j = e & 63;
        float v = ts[j][i];
        __nv_bfloat16 h = __float2bfloat16(v);
        int o = (n * PP + p0 + i) * CC + c0 + j;
        g_xh[o] = h;
        g_xl[o] = __float2bfloat16(v - __bfloat162float(h));
    }
}

// GN + relu on virt [p][n][c] -> bf16 hi/lo [n][p][c]
__global__ __launch_bounds__(256) void split_v_kernel(
    const float* __restrict__ gamma, const float* __restrict__ beta)
{
    const int pn = blockIdx.x;
    const int p = pn >> 8, n = pn & 255;
    const float mu = g_mu[n], rs = g_rs[n];
    for (int c = threadIdx.x; c < CC; c += 256) {
        float raw = g_virt[(p * NN + n) * CC + c];
        float ag = rs * gamma[c];
        float v = fmaxf(fmaf(raw, ag, beta[c] - mu * ag), 0.0f);
        __nv_bfloat16 h = __float2bfloat16(v);
        int o = (n * PP + p) * CC + c;
        g_vbh[o] = h;
        g_vbl[o] = __float2bfloat16(v - __bfloat162float(h));
    }
}

// ---------------- conv as implicit GEMM on legacy mma.sync -----------------
// CTA: M=128 co x N=128 p for one n; K=4608 in 72 chunks of 64 (one shift each).
// smem stage (64KB): Ah[128x128B] Al Bh Bl; XOR-swizzled 16B segs. 2 stages.
#define STG_SZ 65536

__global__ __launch_bounds__(256, 1) void conv_mma_kernel(
    int conv_base, const float* __restrict__ x, float* __restrict__ out)
{
    extern __shared__ char dsm[];
    const unsigned sbase = smem_u32(dsm);
    const int tid = threadIdx.x, wid = tid >> 5, l = tid & 31;
    const int mt = blockIdx.x & 3, pt = blockIdx.x >> 2;
    const int n = blockIdx.y;
    const int conv_sel = conv_base + blockIdx.z;
    const int co0 = mt * 128;
    const __nv_bfloat16* bH = (conv_sel < 3) ? g_xh : g_vbh;
    const __nv_bfloat16* bL = (conv_sel < 3) ? g_xl : g_vbl;
    const int wm = wid >> 1, wn = wid & 1;   // warp tile: M 32 x N 64

    float d[2][8][4];
#pragma unroll
    for (int mi = 0; mi < 2; mi++)
#pragma unroll
        for (int nj = 0; nj < 8; nj++)
#pragma unroll
            for (int rg = 0; rg < 4; rg++) d[mi][nj][rg] = 0.0f;

    // ---- staging (per chunk): A = weights, B = shifted x with zero-fill halo
    auto stage = [&](int c, unsigned stg) {
        const int sh = c >> 3, cb = c & 7;
        const int dh = sh / 3 - 1, dw = sh % 3 - 1;
        const int kbase = c * 64;
#pragma unroll
        for (int i = 0; i < 8; i++) {
            int idx = tid + 256 * i;
            int half = idx >> 10, r = (idx >> 3) & 127, seg = idx & 7;
            const __nv_bfloat16* w = half ? g_wl : g_wh;
            const __nv_bfloat16* src = w + (size_t)(conv_sel * CC + co0 + r) * KTOT + kbase + seg * 8;
            unsigned dst = stg + half * 16384 + r * 128 + ((seg ^ (r & 7)) << 4);
            cp16(dst, src, 16u);
        }
#pragma unroll
        for (int i = 0; i < 8; i++) {
            int idx = tid + 256 * i;
            int half = idx >> 10, r = (idx >> 3) & 127, seg = idx & 7;
            int p = pt * 128 + r;
            int h = (p >> 3) & 7, w2 = p & 7;
            int ph = h + dh, pw = w2 + dw;
            unsigned ok = ((unsigned)ph < 8u) && ((unsigned)pw < 8u);
            int p2 = ok ? ((p & ~63) + ph * 8 + pw) : p;
            const __nv_bfloat16* bb = half ? bL : bH;
            const __nv_bfloat16* src = bb + (size_t)(n * PP + p2) * CC + cb * 64 + seg * 8;
            unsigned dst = stg + 32768 + half * 16384 + r * 128 + ((seg ^ (r & 7)) << 4);
            cp16(dst, src, ok ? 16u : 0u);
        }
        cp_commit();
    };

    stage(0, sbase);
    stage(1, sbase + STG_SZ);

    for (int c = 0; c < NCHUNK; c++) {
        if (c >= NCHUNK - 2) cp_wait0(); else cp_wait1();
        __syncthreads();
        const unsigned stg = sbase + (unsigned)(c & 1) * STG_SZ;
#pragma unroll
        for (int k16 = 0; k16 < 4; k16++) {
            unsigned a[2][2][4];
#pragma unroll
            for (int hf = 0; hf < 2; hf++)
#pragma unroll
                for (int mi = 0; mi < 2; mi++) {
                    int row = wm * 32 + mi * 16 + (l & 15);
                    unsigned ad = stg + hf * 16384 + row * 128 +
                                  (((k16 * 2 + (l >> 4)) ^ (row & 7)) << 4);
                    ldsm4(a[hf][mi], ad);
                }
            unsigned b[2][8][2];
#pragma unroll
            for (int hf = 0; hf < 2; hf++)
#pragma unroll
                for (int j = 0; j < 4; j++) {
                    int row = wn * 64 + j * 16 + (l & 7) + ((l >> 4) << 3);
                    int seg = k16 * 2 + ((l >> 3) & 1);
                    unsigned ad = stg + 32768 + hf * 16384 + row * 128 +
                                  ((seg ^ (row & 7)) << 4);
                    unsigned r4[4];
                    ldsm4(r4, ad);
                    b[hf][2 * j][0] = r4[0]; b[hf][2 * j][1] = r4[1];
                    b[hf][2 * j + 1][0] = r4[2]; b[hf][2 * j + 1][1] = r4[3];
                }
#pragma unroll
            for (int mi = 0; mi < 2; mi++)
#pragma unroll
                for (int nj = 0; nj < 8; nj++) {
                    mma16816(d[mi][nj], a[0][mi], b[0][nj]);   // hi*hi
                    mma16816(d[mi][nj], a[0][mi], b[1][nj]);   // hi*lo
                    mma16816(d[mi][nj], a[1][mi], b[0][nj]);   // lo*hi
                }
        }
        __syncthreads();
        if (c + 2 < NCHUNK) stage(c + 2, stg);
    }

    // ---- epilogue: stage accums as ep[co][p] (pitch 129), then coalesced out
    cp_wait0();
    __syncthreads();
    float* ep = (float*)dsm;
#pragma unroll
    for (int mi = 0; mi < 2; mi++)
#pragma unroll
        for (int nj = 0; nj < 8; nj++)
#pragma unroll
            for (int rg = 0; rg < 4; rg++) {
                int row = wm * 32 + mi * 16 + (l >> 2) + (rg >> 1) * 8;  // co
                int col = wn * 64 + nj * 8 + (l & 3) * 2 + (rg & 1);     // p
                ep[row * 129 + col] = d[mi][nj][rg];
            }
    __syncthreads();
    if (conv_sel < 3) {
        float* dst = (conv_sel == 0) ? g_q : (conv_sel == 1) ? g_k : g_v;
        for (int it = wid; it < 128; it += 8) {
            int p = pt * 128 + it;
            float* dr = &dst[((size_t)p * NN + n) * CC + co0];
            for (int c = l; c < 128; c += 32) dr[c] = ep[c * 129 + it];
        }
    } else {
        // out layout [n][c][t][h][w] == [n][c][p] with p linear
        for (int it = wid; it < 128; it += 8) {
            int co = co0 + it;
            size_t o = ((size_t)n * CC + co) * PP + pt * 128;
            for (int pc = l; pc < 128; pc += 32) out[o + pc] = x[o + pc] + ep[it * 129 + pc];
        }
    }
}

// ---------------- attention (fp32 FFMA2, known-good) ----------------
__global__ __launch_bounds__(256) void scores_kernel()
{
    __shared__ __align__(16) float qs[16 * 64];
    __shared__ __align__(16) float ks[16 * 128];
    const int p = blockIdx.y;
    const int jt = blockIdx.x & 1, it = blockIdx.x >> 1;
    const int tid = threadIdx.x, l = tid & 31, wp = tid >> 5;
    ull acc[8][2];
#pragma unroll
    for (int r = 0; r < 8; r++) { acc[r][0] = 0ULL; acc[r][1] = 0ULL; }
    for (int c0 = 0; c0 < CC; c0 += 16) {
        for (int idx = tid; idx < 1024; idx += 256) {
            int i_loc = idx >> 4, kk = idx & 15;
            qs[kk * 64 + i_loc] = g_q[(p * NN + it * 64 + i_loc) * CC + c0 + kk];
        }
        for (int idx = tid; idx < 2048; idx += 256) {
            int j_loc = idx >> 4, kk = idx & 15;
            ks[kk * 128 + j_loc] = g_k[(p * NN + jt * 128 + j_loc) * CC + c0 + kk];
        }
        __syncthreads();
#pragma unroll
        for (int kk = 0; kk < 16; kk++) {
            ull kA = *(const ull*)&ks[kk * 128 + 2 * l];
            ull kB = *(const ull*)&ks[kk * 128 + 64 + 2 * l];
#pragma unroll
            for (int r = 0; r < 8; r++) {
                ull qb = pack2(qs[kk * 64 + wp * 8 + r]);
                acc[r][0] = fma2(qb, kA, acc[r][0]);
                acc[r][1] = fma2(qb, kB, acc[r][1]);
            }
        }
        __syncthreads();
    }
    const float scale = rsqrtf((float)CC);
#pragma unroll
    for (int r = 0; r < 8; r++)
#pragma unroll
        for (int hf = 0; hf < 2; hf++) {
            float lo, hi; unpack2(acc[r][hf], lo, hi);
            const int i = it * 64 + wp * 8 + r;
            const int j = jt * 128 + hf * 64 + 2 * l;
            float2 val; val.x = lo * scale; val.y = hi * scale;
            *(float2*)&g_att[(p * NN + i) * NN + j] = val;
        }
}

__global__ __launch_bounds__(256) void softmax_kernel(const int* __restrict__ roi)
{
    __shared__ int rg[256];
    const int tid = threadIdx.x, l = tid & 31, wp = tid >> 5;
    rg[tid] = roi[tid];
    __syncthreads();
    const int row = blockIdx.x * 8 + wp;
    const int p = row >> 8, i = row & 255;
    const int gi = rg[i];
    float* rowp = &g_att[(p * NN + i) * NN];
    float v[8];
#pragma unroll
    for (int jj = 0; jj < 8; jj++) {
        int j = jj * 32 + l;
        float s = rowp[j];
        v[jj] = (rg[j] == gi) ? s : -1e30f;
    }
    float m = v[0];
#pragma unroll
    for (int jj = 1; jj < 8; jj++) m = fmaxf(m, v[jj]);
#pragma unroll
    for (int off = 16; off; off >>= 1) m = fmaxf(m, __shfl_xor_sync(0xffffffffu, m, off));
    float e[8]; float sum = 0.0f;
#pragma unroll
    for (int jj = 0; jj < 8; jj++) { e[jj] = expf(v[jj] - m); sum += e[jj]; }
#pragma unroll
    for (int off = 16; off; off >>= 1) sum += __shfl_xor_sync(0xffffffffu, sum, off);
    const float inv = 1.0f / sum;
#pragma unroll
    for (int jj = 0; jj < 8; jj++) rowp[jj * 32 + l] = e[jj] * inv;
}

__global__ __launch_bounds__(256) void virt_kernel()
{
    __shared__ __align__(16) float as_[16 * 64];
    __shared__ __align__(16) float vs_[16 * 128];
    const int p = blockIdx.y;
    const int ct = blockIdx.x & 3, it = blockIdx.x >> 2;
    const int tid = threadIdx.x, l = tid & 31, wp = tid >> 5;
    ull acc[8][2];
#pragma unroll
    for (int r = 0; r < 8; r++) { acc[r][0] = 0ULL; acc[r][1] = 0ULL; }
    for (int j0 = 0; j0 < NN; j0 += 16) {
        for (int idx = tid; idx < 1024; idx += 256) {
            int i_loc = idx >> 4, jj = idx & 15;
            as_[jj * 64 + i_loc] = g_att[(p * NN + it * 64 + i_loc) * NN + j0 + jj];
        }
        for (int idx = tid; idx < 2048; idx += 256) {
            int jj = idx >> 7, cl = idx & 127;
            vs_[jj * 128 + cl] = g_v[(p * NN + j0 + jj) * CC + ct * 128 + cl];
        }
        __syncthreads();
#pragma unroll
        for (int jj = 0; jj < 16; jj++) {
            ull vA = *(const ull*)&vs_[jj * 128 + 2 * l];
            ull vB = *(const ull*)&vs_[jj * 128 + 64 + 2 * l];
#pragma unroll
            for (int r = 0; r < 8; r++) {
                ull ab = pack2(as_[jj * 64 + wp * 8 + r]);
                acc[r][0] = fma2(ab, vA, acc[r][0]);
                acc[r][1] = fma2(ab, vB, acc[r][1]);
            }
        }
        __syncthreads();
    }
#pragma unroll
    for (int r = 0; r < 8; r++) {
        const int i = it * 64 + wp * 8 + r;
#pragma unroll
        for (int hf = 0; hf < 2; hf++) {
            const int c = ct * 128 + hf * 64 + 2 * l;
            *(ull*)&g_virt[(p * NN + i) * CC + c] = acc[r][hf];
        }
    }
}

__global__ __launch_bounds__(256) void stats_kernel()
{
    __shared__ float r1[256];
    __shared__ float r2[256];
    const int n = blockIdx.x, tid = threadIdx.x;
    float s = 0.0f, s2 = 0.0f;
    for (int e = tid; e < PP * CC; e += 256) {
        int p = e >> 9, c = e & 511;
        float v = g_virt[(p * NN + n) * CC + c];
        s += v; s2 += v * v;
    }
    r1[tid] = s; r2[tid] = s2;
    __syncthreads();
    for (int off = 128; off; off >>= 1) {
        if (tid < off) { r1[tid] += r1[tid + off]; r2[tid] += r2[tid + off]; }
        __syncthreads();
    }
    if (tid == 0) {
        const float invN = 1.0f / (float)(PP * CC);
        float mu = r1[0] * invN;
        float var = r2[0] * invN - mu * mu;
        g_mu[n] = mu;
        g_rs[n] = rsqrtf(var + 1e-5f);
    }
}

// ---------------- host ----------------
extern "C" void kernel_launch(void* const* d_in, const int* in_sizes, int n_in,
                              void* d_out, int out_size)
{
    const float* x     = (const float*)d_in[0];
    const int*   roi   = (const int*)d_in[1];
    const float* Wq    = (const float*)d_in[2];
    const float* Wk    = (const float*)d_in[3];
    const float* Wv    = (const float*)d_in[4];
    const float* Wc    = (const float*)d_in[5];
    const float* gamma = (const float*)d_in[6];
    const float* beta  = (const float*)d_in[7];
    float* out = (float*)d_out;

    static int configured = 0;
    if (!configured) {
        cudaFuncSetAttribute(conv_mma_kernel,
                             cudaFuncAttributeMaxDynamicSharedMemorySize, 2 * STG_SZ);
        configured = 1;
    }

    split_w_kernel<<<36864, 256>>>(Wq, Wk, Wv, Wc);
    split_x_kernel<<<dim3(4, 8, 256), 256>>>(x);
    conv_mma_kernel<<<dim3(8, 256, 3), 256, 2 * STG_SZ>>>(0, x, out);   // q,k,v
    scores_kernel<<<dim3(8, 256), 256>>>();
    softmax_kernel<<<8192, 256>>>(roi);
    virt_kernel<<<dim3(16, 256), 256>>>();
    stats_kernel<<<256, 256>>>();
    split_v_kernel<<<65536, 256>>>(gamma, beta);
    conv_mma_kernel<<<dim3(8, 256, 1), 256, 2 * STG_SZ>>>(3, x, out);   // out conv
}

// round 10
// speedup vs baseline: 5.2557x; 1.0592x over previous
#include <cuda_runtime.h>
#include <cuda_bf16.h>
#include <math.h>

#define NN   256
#define CC   512
#define PP   256
#define KTOT 4608
#define NCHUNK 72
#define STG_SZ 65536

typedef unsigned long long ull;

// ---------------- scratch ----------------
__device__ __align__(1024) __nv_bfloat16 g_qh[PP * NN * CC];
__device__ __align__(1024) __nv_bfloat16 g_ql[PP * NN * CC];
__device__ __align__(1024) __nv_bfloat16 g_kh[PP * NN * CC];
__device__ __align__(1024) __nv_bfloat16 g_kl[PP * NN * CC];
__device__ __align__(1024) __nv_bfloat16 g_vh[PP * NN * CC];
__device__ __align__(1024) __nv_bfloat16 g_vl[PP * NN * CC];
__device__ __align__(1024) float g_att[PP * NN * NN];
__device__ __align__(1024) __nv_bfloat16 g_atth[PP * NN * NN];
__device__ __align__(1024) __nv_bfloat16 g_attl[PP * NN * NN];
__device__ __align__(1024) float g_virt[PP * NN * CC];
__device__ __align__(1024) __nv_bfloat16 g_wh[4 * CC * KTOT];
__device__ __align__(1024) __nv_bfloat16 g_wl[4 * CC * KTOT];
__device__ __align__(1024) __nv_bfloat16 g_xh[NN * PP * CC];
__device__ __align__(1024) __nv_bfloat16 g_xl[NN * PP * CC];
__device__ __align__(1024) __nv_bfloat16 g_vbh[NN * PP * CC];
__device__ __align__(1024) __nv_bfloat16 g_vbl[NN * PP * CC];
__device__ float g_mu[NN];
__device__ float g_rs[NN];

// ---------------- sm_80-level PTX helpers ----------------
__device__ __forceinline__ unsigned smem_u32(const void* p) {
    unsigned a;
    asm("{ .reg .u64 t; cvta.to.shared.u64 t, %1; cvt.u32.u64 %0, t; }" : "=r"(a) : "l"(p));
    return a;
}
__device__ __forceinline__ void cp16(unsigned dst, const void* src, unsigned sz) {
    asm volatile("cp.async.cg.shared.global [%0], [%1], 16, %2;" :: "r"(dst), "l"(src), "r"(sz) : "memory");
}
__device__ __forceinline__ void cp_commit() { asm volatile("cp.async.commit_group;" ::: "memory"); }
__device__ __forceinline__ void cp_wait1()  { asm volatile("cp.async.wait_group 1;" ::: "memory"); }
__device__ __forceinline__ void cp_wait0()  { asm volatile("cp.async.wait_group 0;" ::: "memory"); }
__device__ __forceinline__ void ldsm4(unsigned* r, unsigned a) {
    asm volatile("ldmatrix.sync.aligned.m8n8.x4.shared.b16 {%0,%1,%2,%3}, [%4];"
                 : "=r"(r[0]), "=r"(r[1]), "=r"(r[2]), "=r"(r[3]) : "r"(a));
}
__device__ __forceinline__ void ldsm4t(unsigned* r, unsigned a) {
    asm volatile("ldmatrix.sync.aligned.m8n8.x4.trans.shared.b16 {%0,%1,%2,%3}, [%4];"
                 : "=r"(r[0]), "=r"(r[1]), "=r"(r[2]), "=r"(r[3]) : "r"(a));
}
__device__ __forceinline__ void mma16816(float* d, const unsigned* a, const unsigned* b) {
    asm volatile(
        "mma.sync.aligned.m16n8k16.row.col.f32.bf16.bf16.f32 "
        "{%0,%1,%2,%3}, {%4,%5,%6,%7}, {%8,%9}, {%0,%1,%2,%3};"
        : "+f"(d[0]), "+f"(d[1]), "+f"(d[2]), "+f"(d[3])
        : "r"(a[0]), "r"(a[1]), "r"(a[2]), "r"(a[3]), "r"(b[0]), "r"(b[1]));
}

// ---------------- conversions ----------------
__global__ __launch_bounds__(256) void split_w_kernel(
    const float* __restrict__ Wq, const float* __restrict__ Wk,
    const float* __restrict__ Wv, const float* __restrict__ Wc)
{
    int idx = blockIdx.x * 256 + threadIdx.x;
    int conv = idx / (CC * KTOT);
    int r = idx - conv * (CC * KTOT);
    int co = r / KTOT, k = r - co * KTOT;
    int s = k >> 9, ci = k & 511;
    const float* W = (conv == 0) ? Wq : (conv == 1) ? Wk : (conv == 2) ? Wv : Wc;
    float v = W[(co * CC + ci) * 9 + s];
    __nv_bfloat16 h = __float2bfloat16(v);
    g_wh[idx] = h;
    g_wl[idx] = __float2bfloat16(v - __bfloat162float(h));
}

__global__ __launch_bounds__(256) void split_x_kernel(const float* __restrict__ x)
{
    __shared__ float ts[64][65];
    const int n = blockIdx.z, c0 = blockIdx.y * 64, p0 = blockIdx.x * 64;
    const int tid = threadIdx.x;
    for (int e = tid; e < 4096; e += 256) {
        int i = e >> 6, j = e & 63;
        ts[i][j] = x[(n * CC + c0 + i) * PP + p0 + j];
    }
    __syncthreads();
    for (int e = tid; e < 4096; e += 256) {
        int i = e >> 6, j = e & 63;
        float v = ts[j][i];
        __nv_bfloat16 h = __float2bfloat16(v);
        int o = (n * PP + p0 + i) * CC + c0 + j;
        g_xh[o] = h;
        g_xl[o] = __float2bfloat16(v - __bfloat162float(h));
    }
}

__global__ __launch_bounds__(256) void split_v_kernel(
    const float* __restrict__ gamma, const float* __restrict__ beta)
{
    const int pn = blockIdx.x;
    const int p = pn >> 8, n = pn & 255;
    const float mu = g_mu[n], rs = g_rs[n];
    for (int c = threadIdx.x; c < CC; c += 256) {
        float raw = g_virt[(p * NN + n) * CC + c];
        float ag = rs * gamma[c];
        float v = fmaxf(fmaf(raw, ag, beta[c] - mu * ag), 0.0f);
        __nv_bfloat16 h = __float2bfloat16(v);
        int o = (n * PP + p) * CC + c;
        g_vbh[o] = h;
        g_vbl[o] = __float2bfloat16(v - __bfloat162float(h));
    }
}

// ---------------- conv implicit GEMM (3-stage, 1 sync/chunk) ----------------
__global__ __launch_bounds__(256, 1) void conv_mma_kernel(
    int conv_base, const float* __restrict__ x, float* __restrict__ out)
{
    extern __shared__ char dsm[];
    const unsigned sbase = smem_u32(dsm);
    const int tid = threadIdx.x, wid = tid >> 5, l = tid & 31;
    const int mt = blockIdx.x & 3, pt = blockIdx.x >> 2;
    const int n = blockIdx.y;
    const int conv_sel = conv_base + blockIdx.z;
    const int co0 = mt * 128;
    const __nv_bfloat16* bH = (conv_sel < 3) ? g_xh : g_vbh;
    const __nv_bfloat16* bL = (conv_sel < 3) ? g_xl : g_vbl;
    const int wm = wid >> 1, wn = wid & 1;

    float d[2][8][4];
#pragma unroll
    for (int mi = 0; mi < 2; mi++)
#pragma unroll
        for (int nj = 0; nj < 8; nj++)
#pragma unroll
            for (int rg = 0; rg < 4; rg++) d[mi][nj][rg] = 0.0f;

    auto stage = [&](int c) {
        const unsigned stg = sbase + (unsigned)(c % 3) * STG_SZ;
        const int sh = c >> 3, cb = c & 7;
        const int dh = sh / 3 - 1, dw = sh % 3 - 1;
        const int kbase = c * 64;
#pragma unroll
        for (int i = 0; i < 8; i++) {
            int idx = tid + 256 * i;
            int half = idx >> 10, r = (idx >> 3) & 127, seg = idx & 7;
            const __nv_bfloat16* w = half ? g_wl : g_wh;
            const __nv_bfloat16* src = w + (size_t)(conv_sel * CC + co0 + r) * KTOT + kbase + seg * 8;
            cp16(stg + half * 16384 + r * 128 + ((seg ^ (r & 7)) << 4), src, 16u);
        }
#pragma unroll
        for (int i = 0; i < 8; i++) {
            int idx = tid + 256 * i;
            int half = idx >> 10, r = (idx >> 3) & 127, seg = idx & 7;
            int p = pt * 128 + r;
            int h = (p >> 3) & 7, w2 = p & 7;
            int ph = h + dh, pw = w2 + dw;
            unsigned ok = ((unsigned)ph < 8u) && ((unsigned)pw < 8u);
            int p2 = ok ? ((p & ~63) + ph * 8 + pw) : p;
            const __nv_bfloat16* bb = half ? bL : bH;
            const __nv_bfloat16* src = bb + (size_t)(n * PP + p2) * CC + cb * 64 + seg * 8;
            cp16(stg + 32768 + half * 16384 + r * 128 + ((seg ^ (r & 7)) << 4), src, ok ? 16u : 0u);
        }
        cp_commit();
    };

    stage(0); stage(1);

    for (int c = 0; c < NCHUNK; c++) {
        if (c + 1 >= NCHUNK) cp_wait0(); else cp_wait1();
        __syncthreads();
        if (c + 2 < NCHUNK) stage(c + 2);
        const unsigned stg = sbase + (unsigned)(c % 3) * STG_SZ;
#pragma unroll
        for (int k16 = 0; k16 < 4; k16++) {
            unsigned a[2][2][4];
#pragma unroll
            for (int hf = 0; hf < 2; hf++)
#pragma unroll
                for (int mi = 0; mi < 2; mi++) {
                    int row = wm * 32 + mi * 16 + (l & 15);
                    ldsm4(a[hf][mi], stg + hf * 16384 + row * 128 +
                                     (((k16 * 2 + (l >> 4)) ^ (row & 7)) << 4));
                }
            unsigned b[2][8][2];
#pragma unroll
            for (int hf = 0; hf < 2; hf++)
#pragma unroll
                for (int j = 0; j < 4; j++) {
                    int row = wn * 64 + j * 16 + (l & 7) + ((l >> 4) << 3);
                    int seg = k16 * 2 + ((l >> 3) & 1);
                    unsigned r4[4];
                    ldsm4(r4, stg + 32768 + hf * 16384 + row * 128 + ((seg ^ (row & 7)) << 4));
                    b[hf][2 * j][0] = r4[0]; b[hf][2 * j][1] = r4[1];
                    b[hf][2 * j + 1][0] = r4[2]; b[hf][2 * j + 1][1] = r4[3];
                }
#pragma unroll
            for (int mi = 0; mi < 2; mi++)
#pragma unroll
                for (int nj = 0; nj < 8; nj++) {
                    mma16816(d[mi][nj], a[0][mi], b[0][nj]);
                    mma16816(d[mi][nj], a[0][mi], b[1][nj]);
                    mma16816(d[mi][nj], a[1][mi], b[0][nj]);
                }
        }
    }

    cp_wait0();
    __syncthreads();
    float* ep = (float*)dsm;
#pragma unroll
    for (int mi = 0; mi < 2; mi++)
#pragma unroll
        for (int nj = 0; nj < 8; nj++)
#pragma unroll
            for (int rg = 0; rg < 4; rg++) {
                int row = wm * 32 + mi * 16 + (l >> 2) + (rg >> 1) * 8;  // co
                int col = wn * 64 + nj * 8 + (l & 3) * 2 + (rg & 1);     // p
                ep[row * 129 + col] = d[mi][nj][rg];
            }
    __syncthreads();
    if (conv_sel < 3) {
        __nv_bfloat16* dh2 = (conv_sel == 0) ? g_qh : (conv_sel == 1) ? g_kh : g_vh;
        __nv_bfloat16* dl2 = (conv_sel == 0) ? g_ql : (conv_sel == 1) ? g_kl : g_vl;
        for (int it = wid; it < 128; it += 8) {
            int p = pt * 128 + it;
            size_t o = ((size_t)p * NN + n) * CC + co0;
            for (int c = l; c < 128; c += 32) {
                float val = ep[c * 129 + it];
                __nv_bfloat16 h = __float2bfloat16(val);
                dh2[o + c] = h;
                dl2[o + c] = __float2bfloat16(val - __bfloat162float(h));
            }
        }
    } else {
        for (int it = wid; it < 128; it += 8) {
            size_t o = ((size_t)n * CC + co0 + it) * PP + pt * 128;
            for (int pc = l; pc < 128; pc += 32) out[o + pc] = x[o + pc] + ep[it * 129 + pc];
        }
    }
}

// ---------------- scores: S_p = (Q K^T)*scale on mma.sync ----------------
__global__ __launch_bounds__(256, 1) void scores_mma_kernel()
{
    extern __shared__ char dsm[];
    const unsigned sbase = smem_u32(dsm);
    const int tid = threadIdx.x, wid = tid >> 5, l = tid & 31;
    const int it = blockIdx.x & 1, jt = blockIdx.x >> 1;
    const int p = blockIdx.y;
    const int wm = wid >> 1, wn = wid & 1;
    const int i0 = it * 128, j0 = jt * 128;

    float d[2][8][4];
#pragma unroll
    for (int mi = 0; mi < 2; mi++)
#pragma unroll
        for (int nj = 0; nj < 8; nj++)
#pragma unroll
            for (int rg = 0; rg < 4; rg++) d[mi][nj][rg] = 0.0f;

    auto stage = [&](int c) {
        const unsigned stg = sbase + (unsigned)(c % 3) * STG_SZ;
        const int kb = c * 64;
#pragma unroll
        for (int i = 0; i < 8; i++) {
            int idx = tid + 256 * i;
            int half = idx >> 10, r = (idx >> 3) & 127, seg = idx & 7;
            const __nv_bfloat16* src = (half ? g_ql : g_qh) + (size_t)(p * NN + i0 + r) * CC + kb + seg * 8;
            cp16(stg + half * 16384 + r * 128 + ((seg ^ (r & 7)) << 4), src, 16u);
        }
#pragma unroll
        for (int i = 0; i < 8; i++) {
            int idx = tid + 256 * i;
            int half = idx >> 10, r = (idx >> 3) & 127, seg = idx & 7;
            const __nv_bfloat16* src = (half ? g_kl : g_kh) + (size_t)(p * NN + j0 + r) * CC + kb + seg * 8;
            cp16(stg + 32768 + half * 16384 + r * 128 + ((seg ^ (r & 7)) << 4), src, 16u);
        }
        cp_commit();
    };

    stage(0); stage(1);
    for (int c = 0; c < 8; c++) {
        if (c + 1 >= 8) cp_wait0(); else cp_wait1();
        __syncthreads();
        if (c + 2 < 8) stage(c + 2);
        const unsigned stg = sbase + (unsigned)(c % 3) * STG_SZ;
#pragma unroll
        for (int k16 = 0; k16 < 4; k16++) {
            unsigned a[2][2][4];
#pragma unroll
            for (int hf = 0; hf < 2; hf++)
#pragma unroll
                for (int mi = 0; mi < 2; mi++) {
                    int row = wm * 32 + mi * 16 + (l & 15);
                    ldsm4(a[hf][mi], stg + hf * 16384 + row * 128 +
                                     (((k16 * 2 + (l >> 4)) ^ (row & 7)) << 4));
                }
            unsigned b[2][8][2];
#pragma unroll
            for (int hf = 0; hf < 2; hf++)
#pragma unroll
                for (int j = 0; j < 4; j++) {
                    int row = wn * 64 + j * 16 + (l & 7) + ((l >> 4) << 3);
                    int seg = k16 * 2 + ((l >> 3) & 1);
                    unsigned r4[4];
                    ldsm4(r4, stg + 32768 + hf * 16384 + row * 128 + ((seg ^ (row & 7)) << 4));
                    b[hf][2 * j][0] = r4[0]; b[hf][2 * j][1] = r4[1];
                    b[hf][2 * j + 1][0] = r4[2]; b[hf][2 * j + 1][1] = r4[3];
                }
#pragma unroll
            for (int mi = 0; mi < 2; mi++)
#pragma unroll
                for (int nj = 0; nj < 8; nj++) {
                    mma16816(d[mi][nj], a[0][mi], b[0][nj]);
                    mma16816(d[mi][nj], a[0][mi], b[1][nj]);
                    mma16816(d[mi][nj], a[1][mi], b[0][nj]);
                }
        }
    }
    cp_wait0();
    __syncthreads();
    float* ep = (float*)dsm;
    const float scale = rsqrtf((float)CC);
#pragma unroll
    for (int mi = 0; mi < 2; mi++)
#pragma unroll
        for (int nj = 0; nj < 8; nj++)
#pragma unroll
            for (int rg = 0; rg < 4; rg++) {
                int row = wm * 32 + mi * 16 + (l >> 2) + (rg >> 1) * 8;
                int col = wn * 64 + nj * 8 + (l & 3) * 2 + (rg & 1);
                ep[row * 129 + col] = d[mi][nj][rg] * scale;
            }
    __syncthreads();
    for (int r = wid; r < 128; r += 8) {
        float* dr = &g_att[((size_t)p * NN + i0 + r) * NN + j0];
        for (int c = l; c < 128; c += 32) dr[c] = ep[r * 129 + c];
    }
}

// ---------------- softmax (masked), emits bf16 hi/lo ----------------
__global__ __launch_bounds__(256) void softmax_kernel(const int* __restrict__ roi)
{
    __shared__ int rg[256];
    const int tid = threadIdx.x, l = tid & 31, wp = tid >> 5;
    rg[tid] = roi[tid];
    __syncthreads();
    const int row = blockIdx.x * 8 + wp;
    const int p = row >> 8, i = row & 255;
    const int gi = rg[i];
    const size_t ro = ((size_t)p * NN + i) * NN;
    float v[8];
#pragma unroll
    for (int jj = 0; jj < 8; jj++) {
        int j = jj * 32 + l;
        float s = g_att[ro + j];
        v[jj] = (rg[j] == gi) ? s : -1e30f;
    }
    float m = v[0];
#pragma unroll
    for (int jj = 1; jj < 8; jj++) m = fmaxf(m, v[jj]);
#pragma unroll
    for (int off = 16; off; off >>= 1) m = fmaxf(m, __shfl_xor_sync(0xffffffffu, m, off));
    float e[8]; float sum = 0.0f;
#pragma unroll
    for (int jj = 0; jj < 8; jj++) { e[jj] = expf(v[jj] - m); sum += e[jj]; }
#pragma unroll
    for (int off = 16; off; off >>= 1) sum += __shfl_xor_sync(0xffffffffu, sum, off);
    const float inv = 1.0f / sum;
#pragma unroll
    for (int jj = 0; jj < 8; jj++) {
        float a = e[jj] * inv;
        __nv_bfloat16 h = __float2bfloat16(a);
        g_atth[ro + jj * 32 + l] = h;
        g_attl[ro + jj * 32 + l] = __float2bfloat16(a - __bfloat162float(h));
    }
}

// ---------------- virt = att · V on mma.sync (B via ldmatrix.trans) --------
__global__ __launch_bounds__(256, 1) void virt_mma_kernel()
{
    extern __shared__ char dsm[];
    const unsigned sbase = smem_u32(dsm);
    const int tid = threadIdx.x, wid = tid >> 5, l = tid & 31;
    const int it = blockIdx.x & 1, ct = blockIdx.x >> 1;
    const int p = blockIdx.y;
    const int wm = wid >> 1, wn = wid & 1;
    const int i0 = it * 128, c0 = ct * 128;

    float d[2][8][4];
#pragma unroll
    for (int mi = 0; mi < 2; mi++)
#pragma unroll
        for (int nj = 0; nj < 8; nj++)
#pragma unroll
            for (int rg = 0; rg < 4; rg++) d[mi][nj][rg] = 0.0f;

    auto stage = [&](int c) {
        const unsigned stg = sbase + (unsigned)(c % 3) * STG_SZ;
        const int j0 = c * 64;
        // A: att rows i (128 x 64j, 128B rows)
#pragma unroll
        for (int i = 0; i < 8; i++) {
            int idx = tid + 256 * i;
            int half = idx >> 10, r = (idx >> 3) & 127, seg = idx & 7;
            const __nv_bfloat16* src = (half ? g_attl : g_atth) + (size_t)(p * NN + i0 + r) * NN + j0 + seg * 8;
            cp16(stg + half * 16384 + r * 128 + ((seg ^ (r & 7)) << 4), src, 16u);
        }
        // B: V rows j (64 x 128c, 256B rows)
#pragma unroll
        for (int i = 0; i < 8; i++) {
            int idx = tid + 256 * i;
            int half = idx >> 10, rem = idx & 1023;
            int r = rem >> 4, seg = rem & 15;
            const __nv_bfloat16* src = (half ? g_vl : g_vh) + (size_t)(p * NN + j0 + r) * CC + c0 + seg * 8;
            cp16(stg + 32768 + half * 16384 + r * 256 + ((seg ^ ((r & 7) << 1)) << 4), src, 16u);
        }
        cp_commit();
    };

    stage(0); stage(1);
    for (int c = 0; c < 4; c++) {
        if (c + 1 >= 4) cp_wait0(); else cp_wait1();
        __syncthreads();
        if (c + 2 < 4) stage(c + 2);
        const unsigned stg = sbase + (unsigned)(c % 3) * STG_SZ;
#pragma unroll
        for (int k16 = 0; k16 < 4; k16++) {
            unsigned a[2][2][4];
#pragma unroll
            for (int hf = 0; hf < 2; hf++)
#pragma unroll
                for (int mi = 0; mi < 2; mi++) {
                    int row = wm * 32 + mi * 16 + (l & 15);
                    ldsm4(a[hf][mi], stg + hf * 16384 + row * 128 +
                                     (((k16 * 2 + (l >> 4)) ^ (row & 7)) << 4));
                }
            unsigned b[2][8][2];
#pragma unroll
            for (int hf = 0; hf < 2; hf++)
#pragma unroll
                for (int cg = 0; cg < 4; cg++) {
                    int tileid = l >> 3;
                    int jr = (l & 7) + (tileid & 1) * 8;
                    int row = k16 * 16 + jr;
                    int seg = wn * 8 + cg * 2 + (tileid >> 1);
                    unsigned r4[4];
                    ldsm4t(r4, stg + 32768 + hf * 16384 + row * 256 +
                               ((seg ^ ((row & 7) << 1)) << 4));
                    b[hf][2 * cg][0] = r4[0]; b[hf][2 * cg][1] = r4[1];
                    b[hf][2 * cg + 1][0] = r4[2]; b[hf][2 * cg + 1][1] = r4[3];
                }
#pragma unroll
            for (int mi = 0; mi < 2; mi++)
#pragma unroll
                for (int nj = 0; nj < 8; nj++) {
                    mma16816(d[mi][nj], a[0][mi], b[0][nj]);
                    mma16816(d[mi][nj], a[0][mi], b[1][nj]);
                    mma16816(d[mi][nj], a[1][mi], b[0][nj]);
                }
        }
    }
    cp_wait0();
    __syncthreads();
    float* ep = (float*)dsm;
#pragma unroll
    for (int mi = 0; mi < 2; mi++)
#pragma unroll
        for (int nj = 0; nj < 8; nj++)
#pragma unroll
            for (int rg = 0; rg < 4; rg++) {
                int row = wm * 32 + mi * 16 + (l >> 2) + (rg >> 1) * 8;  // i
                int col = wn * 64 + nj * 8 + (l & 3) * 2 + (rg & 1);     // c
                ep[row * 129 + col] = d[mi][nj][rg];
            }
    __syncthreads();
    for (int r = wid; r < 128; r += 8) {
        float* dr = &g_virt[((size_t)p * NN + i0 + r) * CC + c0];
        for (int c = l; c < 128; c += 32) dr[c] = ep[r * 129 + c];
    }
}

// ---------------- GN stats ----------------
__global__ __launch_bounds__(256) void stats_kernel()
{
    __shared__ float r1[256];
    __shared__ float r2[256];
    const int n = blockIdx.x, tid = threadIdx.x;
    float s = 0.0f, s2 = 0.0f;
    for (int e = tid; e < PP * CC; e += 256) {
        int p = e >> 9, c = e & 511;
        float v = g_virt[(p * NN + n) * CC + c];
        s += v; s2 += v * v;
    }
    r1[tid] = s; r2[tid] = s2;
    __syncthreads();
    for (int off = 128; off; off >>= 1) {
        if (tid < off) { r1[tid] += r1[tid + off]; r2[tid] += r2[tid + off]; }
        __syncthreads();
    }
    if (tid == 0) {
        const float invN = 1.0f / (float)(PP * CC);
        float mu = r1[0] * invN;
        float var = r2[0] * invN - mu * mu;
        g_mu[n] = mu;
        g_rs[n] = rsqrtf(var + 1e-5f);
    }
}

// ---------------- host ----------------
extern "C" void kernel_launch(void* const* d_in, const int* in_sizes, int n_in,
                              void* d_out, int out_size)
{
    const float* x     = (const float*)d_in[0];
    const int*   roi   = (const int*)d_in[1];
    const float* Wq    = (const float*)d_in[2];
    const float* Wk    = (const float*)d_in[3];
    const float* Wv    = (const float*)d_in[4];
    const float* Wc    = (const float*)d_in[5];
    const float* gamma = (const float*)d_in[6];
    const float* beta  = (const float*)d_in[7];
    float* out = (float*)d_out;

    cudaFuncSetAttribute(conv_mma_kernel,   cudaFuncAttributeMaxDynamicSharedMemorySize, 3 * STG_SZ);
    cudaFuncSetAttribute(scores_mma_kernel, cudaFuncAttributeMaxDynamicSharedMemorySize, 3 * STG_SZ);
    cudaFuncSetAttribute(virt_mma_kernel,   cudaFuncAttributeMaxDynamicSharedMemorySize, 3 * STG_SZ);

    split_w_kernel<<<36864, 256>>>(Wq, Wk, Wv, Wc);
    split_x_kernel<<<dim3(4, 8, 256), 256>>>(x);
    conv_mma_kernel<<<dim3(8, 256, 3), 256, 3 * STG_SZ>>>(0, x, out);   // q,k,v
    scores_mma_kernel<<<dim3(4, 256), 256, 3 * STG_SZ>>>();
    softmax_kernel<<<8192, 256>>>(roi);
    virt_mma_kernel<<<dim3(8, 256), 256, 3 * STG_SZ>>>();
    stats_kernel<<<256, 256>>>();
    split_v_kernel<<<65536, 256>>>(gamma, beta);
    conv_mma_kernel<<<dim3(8, 256, 1), 256, 3 * STG_SZ>>>(3, x, out);   // out conv
}

// round 11
// speedup vs baseline: 5.8223x; 1.1078x over previous
#include <cuda_runtime.h>
#include <cuda_bf16.h>
#include <math.h>

#define NN   256
#define CC   512
#define PP   256
#define KTOT 4608
#define STG_SZ 65536

typedef unsigned long long ull;

// ---------------- scratch ----------------
__device__ __align__(1024) __nv_bfloat16 g_qh[PP * NN * CC];
__device__ __align__(1024) __nv_bfloat16 g_ql[PP * NN * CC];
__device__ __align__(1024) __nv_bfloat16 g_kh[PP * NN * CC];
__device__ __align__(1024) __nv_bfloat16 g_kl[PP * NN * CC];
__device__ __align__(1024) __nv_bfloat16 g_vh[PP * NN * CC];
__device__ __align__(1024) __nv_bfloat16 g_vl[PP * NN * CC];
__device__ __align__(1024) float g_att[PP * NN * NN];
__device__ __align__(1024) __nv_bfloat16 g_atth[PP * NN * NN];
__device__ __align__(1024) __nv_bfloat16 g_attl[PP * NN * NN];
__device__ __align__(1024) float g_virt[PP * NN * CC];
__device__ __align__(1024) __nv_bfloat16 g_wh[4 * CC * KTOT];
__device__ __align__(1024) __nv_bfloat16 g_wl[4 * CC * KTOT];
__device__ __align__(1024) __nv_bfloat16 g_xh[NN * PP * CC];
__device__ __align__(1024) __nv_bfloat16 g_xl[NN * PP * CC];
__device__ __align__(1024) __nv_bfloat16 g_vbh[NN * PP * CC];
__device__ __align__(1024) __nv_bfloat16 g_vbl[NN * PP * CC];
__device__ float g_mu[NN];
__device__ float g_rs[NN];

// ---------------- sm_80-level PTX helpers ----------------
__device__ __forceinline__ unsigned smem_u32(const void* p) {
    unsigned a;
    asm("{ .reg .u64 t; cvta.to.shared.u64 t, %1; cvt.u32.u64 %0, t; }" : "=r"(a) : "l"(p));
    return a;
}
__device__ __forceinline__ void cp16(unsigned dst, const void* src) {
    asm volatile("cp.async.cg.shared.global [%0], [%1], 16;" :: "r"(dst), "l"(src) : "memory");
}
__device__ __forceinline__ void cp16z(unsigned dst, const void* src, unsigned sz) {
    asm volatile("cp.async.cg.shared.global [%0], [%1], 16, %2;" :: "r"(dst), "l"(src), "r"(sz) : "memory");
}
__device__ __forceinline__ void cp_commit() { asm volatile("cp.async.commit_group;" ::: "memory"); }
__device__ __forceinline__ void cp_wait1()  { asm volatile("cp.async.wait_group 1;" ::: "memory"); }
__device__ __forceinline__ void cp_wait0()  { asm volatile("cp.async.wait_group 0;" ::: "memory"); }
__device__ __forceinline__ void ldsm4(unsigned* r, unsigned a) {
    asm volatile("ldmatrix.sync.aligned.m8n8.x4.shared.b16 {%0,%1,%2,%3}, [%4];"
                 : "=r"(r[0]), "=r"(r[1]), "=r"(r[2]), "=r"(r[3]) : "r"(a));
}
__device__ __forceinline__ void ldsm4t(unsigned* r, unsigned a) {
    asm volatile("ldmatrix.sync.aligned.m8n8.x4.trans.shared.b16 {%0,%1,%2,%3}, [%4];"
                 : "=r"(r[0]), "=r"(r[1]), "=r"(r[2]), "=r"(r[3]) : "r"(a));
}
__device__ __forceinline__ void mma16816(float* d, const unsigned* a, const unsigned* b) {
    asm volatile(
        "mma.sync.aligned.m16n8k16.row.col.f32.bf16.bf16.f32 "
        "{%0,%1,%2,%3}, {%4,%5,%6,%7}, {%8,%9}, {%0,%1,%2,%3};"
        : "+f"(d[0]), "+f"(d[1]), "+f"(d[2]), "+f"(d[3])
        : "r"(a[0]), "r"(a[1]), "r"(a[2]), "r"(a[3]), "r"(b[0]), "r"(b[1]));
}

// ---------------- conversions ----------------
__global__ __launch_bounds__(256) void split_w_kernel(
    const float* __restrict__ Wq, const float* __restrict__ Wk,
    const float* __restrict__ Wv, const float* __restrict__ Wc)
{
    int idx = blockIdx.x * 256 + threadIdx.x;
    int conv = idx / (CC * KTOT);
    int r = idx - conv * (CC * KTOT);
    int co = r / KTOT, k = r - co * KTOT;
    int s = k >> 9, ci = k & 511;
    const float* W = (conv == 0) ? Wq : (conv == 1) ? Wk : (conv == 2) ? Wv : Wc;
    float v = W[(co * CC + ci) * 9 + s];
    __nv_bfloat16 h = __float2bfloat16(v);
    g_wh[idx] = h;
    g_wl[idx] = __float2bfloat16(v - __bfloat162float(h));
}

__global__ __launch_bounds__(256) void split_x_kernel(const float* __restrict__ x)
{
    __shared__ float ts[64][65];
    const int n = blockIdx.z, c0 = blockIdx.y * 64, p0 = blockIdx.x * 64;
    const int tid = threadIdx.x;
    for (int e = tid; e < 4096; e += 256) {
        int i = e >> 6, j = e & 63;
        ts[i][j] = x[(n * CC + c0 + i) * PP + p0 + j];
    }
    __syncthreads();
    for (int e = tid; e < 4096; e += 256) {
        int i = e >> 6, j = e & 63;
        float v = ts[j][i];
        __nv_bfloat16 h = __float2bfloat16(v);
        int o = (n * PP + p0 + i) * CC + c0 + j;
        g_xh[o] = h;
        g_xl[o] = __float2bfloat16(v - __bfloat162float(h));
    }
}

__global__ __launch_bounds__(256) void split_v_kernel(
    const float* __restrict__ gamma, const float* __restrict__ beta)
{
    const int pn = blockIdx.x;
    const int p = pn >> 8, n = pn & 255;
    const float mu = g_mu[n], rs = g_rs[n];
    for (int c = threadIdx.x; c < CC; c += 256) {
        float raw = g_virt[(p * NN + n) * CC + c];
        float ag = rs * gamma[c];
        float v = fmaxf(fmaf(raw, ag, beta[c] - mu * ag), 0.0f);
        __nv_bfloat16 h = __float2bfloat16(v);
        int o = (n * PP + p) * CC + c;
        g_vbh[o] = h;
        g_vbl[o] = __float2bfloat16(v - __bfloat162float(h));
    }
}

// ---------------- conv implicit GEMM, B resident per c-block ----------------
// CTA: M=128 co (mt) x N=256 p (all), one n. iters m=cb*9+sh (72).
// smem: A ring 3x32KB @0 ; B dbuf 2x64KB @98304 ; zero row 128B @229376.
#define A_OFF 0u
#define B_OFF 98304u
#define Z_OFF 229376u
#define CONV_SMEM 229504

__global__ __launch_bounds__(256, 1) void conv_mma_kernel(
    int conv_base, const float* __restrict__ x, float* __restrict__ out)
{
    extern __shared__ char dsm[];
    const unsigned sbase = smem_u32(dsm);
    const int tid = threadIdx.x, wid = tid >> 5, l = tid & 31;
    const int mt = blockIdx.x;
    const int n = blockIdx.y;
    const int conv_sel = conv_base + blockIdx.z;
    const int co0 = mt * 128;
    const __nv_bfloat16* bH = (conv_sel < 3) ? g_xh : g_vbh;
    const __nv_bfloat16* bL = (conv_sel < 3) ? g_xl : g_vbl;
    const int wm = wid >> 1, wn = wid & 1;   // warp tile: M32 x N128

    // zero row
    if (tid < 32) ((float*)(dsm + Z_OFF))[tid] = 0.0f;

    float d[2][16][4];
#pragma unroll
    for (int mi = 0; mi < 2; mi++)
#pragma unroll
        for (int nj = 0; nj < 16; nj++)
#pragma unroll
            for (int rg = 0; rg < 4; rg++) d[mi][nj][rg] = 0.0f;

    auto stageA = [&](int m) {
        const unsigned stg = sbase + A_OFF + (unsigned)(m % 3) * 32768u;
        const int cb = m / 9, sh = m - cb * 9;
        const int kbase = sh * 512 + cb * 64;
#pragma unroll
        for (int i = 0; i < 8; i++) {
            int idx = tid + 256 * i;
            int half = idx >> 10, r = (idx >> 3) & 127, seg = idx & 7;
            const __nv_bfloat16* src = (half ? g_wl : g_wh) +
                (size_t)(conv_sel * CC + co0 + r) * KTOT + kbase + seg * 8;
            cp16(stg + half * 16384 + r * 128 + ((seg ^ (r & 7)) << 4), src);
        }
    };
    auto stageB = [&](int cb, int s) {   // rows 32s..32s+31, both halves
        const unsigned bb = sbase + B_OFF + (unsigned)(cb & 1) * 65536u;
#pragma unroll
        for (int i = 0; i < 2; i++) {
            int idx = tid + 256 * i;            // 0..511
            int half = idx >> 8;
            int rem = idx & 255;
            int r = 32 * s + (rem >> 3), seg = rem & 7;
            const __nv_bfloat16* src = (half ? bL : bH) +
                (size_t)(n * PP + r) * CC + cb * 64 + seg * 8;
            cp16(bb + half * 32768 + r * 128 + ((seg ^ (r & 7)) << 4), src);
        }
    };

    // prologue: B(0) full, A(0), A(1)
    for (int s = 0; s < 8; s++) stageB(0, s);
    cp_commit();
    stageA(0); cp_commit();
    stageA(1); cp_commit();

    const unsigned zb = sbase + Z_OFF;
    const int kb = (l >> 3) & 1;

    for (int m = 0; m < 72; m++) {
        cp_wait1();
        __syncthreads();
        {   // issue next stage group (always exactly one commit per iter)
            if (m + 2 < 72) stageA(m + 2);
            int sh = m % 9, cb = m / 9;
            if (sh < 8 && cb + 1 < 8) stageB(cb + 1, sh);
            cp_commit();
        }
        const int cb = m / 9, sh = m - cb * 9;
        const int dh = sh / 3 - 1, dw = sh % 3 - 1;
        const unsigned astg = sbase + A_OFF + (unsigned)(m % 3) * 32768u;
        const unsigned bb = sbase + B_OFF + (unsigned)(cb & 1) * 65536u;

        // per-ng shifted row bases (shift applied at ldmatrix address)
        unsigned bA[8], hstep[8];
#pragma unroll
        for (int ng = 0; ng < 8; ng++) {
            int p = wn * 128 + ng * 16 + (l & 7) + ((l >> 4) << 3);
            int h = (p >> 3) & 7, w2 = p & 7;
            int ph = h + dh, pw = w2 + dw;
            bool ok = ((unsigned)ph < 8u) && ((unsigned)pw < 8u);
            int p2 = (p & ~63) + ph * 8 + pw;
            bA[ng] = ok ? (bb + (unsigned)(p2 * 128) + (unsigned)(p2 & 7)) : zb;
            hstep[ng] = ok ? 32768u : 0u;
        }

#pragma unroll
        for (int k16 = 0; k16 < 4; k16++) {
            unsigned a[2][2][4];
#pragma unroll
            for (int hf = 0; hf < 2; hf++)
#pragma unroll
                for (int mi = 0; mi < 2; mi++) {
                    int row = wm * 32 + mi * 16 + (l & 15);
                    ldsm4(a[hf][mi], astg + hf * 16384 + row * 128 +
                                     (((k16 * 2 + (l >> 4)) ^ (row & 7)) << 4));
                }
            const int seg = k16 * 2 + kb;
#pragma unroll
            for (int ng = 0; ng < 8; ng++) {
                unsigned sw = bA[ng] & 15u;
                unsigned base = (bA[ng] & ~15u) + (((unsigned)seg ^ sw) << 4);
                unsigned bh4[4], bl4[4];
                ldsm4(bh4, base);
                ldsm4(bl4, base + hstep[ng]);
#pragma unroll
                for (int mi = 0; mi < 2; mi++)
#pragma unroll
                    for (int jj = 0; jj < 2; jj++) {
                        float* dd = d[mi][2 * ng + jj];
                        mma16816(dd, a[0][mi], &bh4[2 * jj]);
                        mma16816(dd, a[0][mi], &bl4[2 * jj]);
                        mma16816(dd, a[1][mi], &bh4[2 * jj]);
                    }
            }
        }
    }

    cp_wait0();
    __syncthreads();
    float* ep = (float*)dsm;   // [co 128][p 256] pitch 257
#pragma unroll
    for (int mi = 0; mi < 2; mi++)
#pragma unroll
        for (int nj = 0; nj < 16; nj++)
#pragma unroll
            for (int rg = 0; rg < 4; rg++) {
                int row = wm * 32 + mi * 16 + (l >> 2) + (rg >> 1) * 8;
                int col = wn * 128 + nj * 8 + (l & 3) * 2 + (rg & 1);
                ep[row * 257 + col] = d[mi][nj][rg];
            }
    __syncthreads();
    if (conv_sel < 3) {
        __nv_bfloat16* dh2 = (conv_sel == 0) ? g_qh : (conv_sel == 1) ? g_kh : g_vh;
        __nv_bfloat16* dl2 = (conv_sel == 0) ? g_ql : (conv_sel == 1) ? g_kl : g_vl;
        for (int p = wid; p < 256; p += 8) {
            size_t o = ((size_t)p * NN + n) * CC + co0;
            for (int c = l; c < 128; c += 32) {
                float val = ep[c * 257 + p];
                __nv_bfloat16 h = __float2bfloat16(val);
                dh2[o + c] = h;
                dl2[o + c] = __float2bfloat16(val - __bfloat162float(h));
            }
        }
    } else {
        for (int r = wid; r < 128; r += 8) {
            size_t o = ((size_t)n * CC + co0 + r) * PP;
            for (int pc = l; pc < 256; pc += 32) out[o + pc] = x[o + pc] + ep[r * 257 + pc];
        }
    }
}

// ---------------- scores: S_p = (Q K^T)*scale on mma.sync ----------------
__global__ __launch_bounds__(256, 1) void scores_mma_kernel()
{
    extern __shared__ char dsm[];
    const unsigned sbase = smem_u32(dsm);
    const int tid = threadIdx.x, wid = tid >> 5, l = tid & 31;
    const int it = blockIdx.x & 1, jt = blockIdx.x >> 1;
    const int p = blockIdx.y;
    const int wm = wid >> 1, wn = wid & 1;
    const int i0 = it * 128, j0 = jt * 128;

    float d[2][8][4];
#pragma unroll
    for (int mi = 0; mi < 2; mi++)
#pragma unroll
        for (int nj = 0; nj < 8; nj++)
#pragma unroll
            for (int rg = 0; rg < 4; rg++) d[mi][nj][rg] = 0.0f;

    auto stage = [&](int c) {
        const unsigned stg = sbase + (unsigned)(c % 3) * STG_SZ;
        const int kbv = c * 64;
#pragma unroll
        for (int i = 0; i < 8; i++) {
            int idx = tid + 256 * i;
            int half = idx >> 10, r = (idx >> 3) & 127, seg = idx & 7;
            const __nv_bfloat16* src = (half ? g_ql : g_qh) + (size_t)(p * NN + i0 + r) * CC + kbv + seg * 8;
            cp16(stg + half * 16384 + r * 128 + ((seg ^ (r & 7)) << 4), src);
        }
#pragma unroll
        for (int i = 0; i < 8; i++) {
            int idx = tid + 256 * i;
            int half = idx >> 10, r = (idx >> 3) & 127, seg = idx & 7;
            const __nv_bfloat16* src = (half ? g_kl : g_kh) + (size_t)(p * NN + j0 + r) * CC + kbv + seg * 8;
            cp16(stg + 32768 + half * 16384 + r * 128 + ((seg ^ (r & 7)) << 4), src);
        }
        cp_commit();
    };

    stage(0); stage(1);
    for (int c = 0; c < 8; c++) {
        if (c + 1 >= 8) cp_wait0(); else cp_wait1();
        __syncthreads();
        if (c + 2 < 8) stage(c + 2);
        const unsigned stg = sbase + (unsigned)(c % 3) * STG_SZ;
#pragma unroll
        for (int k16 = 0; k16 < 4; k16++) {
            unsigned a[2][2][4];
#pragma unroll
            for (int hf = 0; hf < 2; hf++)
#pragma unroll
                for (int mi = 0; mi < 2; mi++) {
                    int row = wm * 32 + mi * 16 + (l & 15);
                    ldsm4(a[hf][mi], stg + hf * 16384 + row * 128 +
                                     (((k16 * 2 + (l >> 4)) ^ (row & 7)) << 4));
                }
            unsigned b[2][8][2];
#pragma unroll
            for (int hf = 0; hf < 2; hf++)
#pragma unroll
                for (int j = 0; j < 4; j++) {
                    int row = wn * 64 + j * 16 + (l & 7) + ((l >> 4) << 3);
                    int seg = k16 * 2 + ((l >> 3) & 1);
                    unsigned r4[4];
                    ldsm4(r4, stg + 32768 + hf * 16384 + row * 128 + ((seg ^ (row & 7)) << 4));
                    b[hf][2 * j][0] = r4[0]; b[hf][2 * j][1] = r4[1];
                    b[hf][2 * j + 1][0] = r4[2]; b[hf][2 * j + 1][1] = r4[3];
                }
#pragma unroll
            for (int mi = 0; mi < 2; mi++)
#pragma unroll
                for (int nj = 0; nj < 8; nj++) {
                    mma16816(d[mi][nj], a[0][mi], b[0][nj]);
                    mma16816(d[mi][nj], a[0][mi], b[1][nj]);
                    mma16816(d[mi][nj], a[1][mi], b[0][nj]);
                }
        }
    }
    cp_wait0();
    __syncthreads();
    float* ep = (float*)dsm;
    const float scale = rsqrtf((float)CC);
#pragma unroll
    for (int mi = 0; mi < 2; mi++)
#pragma unroll
        for (int nj = 0; nj < 8; nj++)
#pragma unroll
            for (int rg = 0; rg < 4; rg++) {
                int row = wm * 32 + mi * 16 + (l >> 2) + (rg >> 1) * 8;
                int col = wn * 64 + nj * 8 + (l & 3) * 2 + (rg & 1);
                ep[row * 129 + col] = d[mi][nj][rg] * scale;
            }
    __syncthreads();
    for (int r = wid; r < 128; r += 8) {
        float* dr = &g_att[((size_t)p * NN + i0 + r) * NN + j0];
        for (int c = l; c < 128; c += 32) dr[c] = ep[r * 129 + c];
    }
}

// ---------------- softmax (masked), emits bf16 hi/lo ----------------
__global__ __launch_bounds__(256) void softmax_kernel(const int* __restrict__ roi)
{
    __shared__ int rg[256];
    const int tid = threadIdx.x, l = tid & 31, wp = tid >> 5;
    rg[tid] = roi[tid];
    __syncthreads();
    const int row = blockIdx.x * 8 + wp;
    const int p = row >> 8, i = row & 255;
    const int gi = rg[i];
    const size_t ro = ((size_t)p * NN + i) * NN;
    float v[8];
#pragma unroll
    for (int jj = 0; jj < 8; jj++) {
        int j = jj * 32 + l;
        float s = g_att[ro + j];
        v[jj] = (rg[j] == gi) ? s : -1e30f;
    }
    float m = v[0];
#pragma unroll
    for (int jj = 1; jj < 8; jj++) m = fmaxf(m, v[jj]);
#pragma unroll
    for (int off = 16; off; off >>= 1) m = fmaxf(m, __shfl_xor_sync(0xffffffffu, m, off));
    float e[8]; float sum = 0.0f;
#pragma unroll
    for (int jj = 0; jj < 8; jj++) { e[jj] = expf(v[jj] - m); sum += e[jj]; }
#pragma unroll
    for (int off = 16; off; off >>= 1) sum += __shfl_xor_sync(0xffffffffu, sum, off);
    const float inv = 1.0f / sum;
#pragma unroll
    for (int jj = 0; jj < 8; jj++) {
        float a = e[jj] * inv;
        __nv_bfloat16 h = __float2bfloat16(a);
        g_atth[ro + jj * 32 + l] = h;
        g_attl[ro + jj * 32 + l] = __float2bfloat16(a - __bfloat162float(h));
    }
}

// ---------------- virt = att · V on mma.sync (B via ldmatrix.trans) --------
__global__ __launch_bounds__(256, 1) void virt_mma_kernel()
{
    extern __shared__ char dsm[];
    const unsigned sbase = smem_u32(dsm);
    const int tid = threadIdx.x, wid = tid >> 5, l = tid & 31;
    const int it = blockIdx.x & 1, ct = blockIdx.x >> 1;
    const int p = blockIdx.y;
    const int wm = wid >> 1, wn = wid & 1;
    const int i0 = it * 128, c0 = ct * 128;

    float d[2][8][4];
#pragma unroll
    for (int mi = 0; mi < 2; mi++)
#pragma unroll
        for (int nj = 0; nj < 8; nj++)
#pragma unroll
            for (int rg = 0; rg < 4; rg++) d[mi][nj][rg] = 0.0f;

    auto stage = [&](int c) {
        const unsigned stg = sbase + (unsigned)(c % 3) * STG_SZ;
        const int j0 = c * 64;
#pragma unroll
        for (int i = 0; i < 8; i++) {
            int idx = tid + 256 * i;
            int half = idx >> 10, r = (idx >> 3) & 127, seg = idx & 7;
            const __nv_bfloat16* src = (half ? g_attl : g_atth) + (size_t)(p * NN + i0 + r) * NN + j0 + seg * 8;
            cp16(stg + half * 16384 + r * 128 + ((seg ^ (r & 7)) << 4), src);
        }
#pragma unroll
        for (int i = 0; i < 8; i++) {
            int idx = tid + 256 * i;
            int half = idx >> 10, rem = idx & 1023;
            int r = rem >> 4, seg = rem & 15;
            const __nv_bfloat16* src = (half ? g_vl : g_vh) + (size_t)(p * NN + j0 + r) * CC + c0 + seg * 8;
            cp16(stg + 32768 + half * 16384 + r * 256 + ((seg ^ ((r & 7) << 1)) << 4), src);
        }
        cp_commit();
    };

    stage(0); stage(1);
    for (int c = 0; c < 4; c++) {
        if (c + 1 >= 4) cp_wait0(); else cp_wait1();
        __syncthreads();
        if (c + 2 < 4) stage(c + 2);
        const unsigned stg = sbase + (unsigned)(c % 3) * STG_SZ;
#pragma unroll
        for (int k16 = 0; k16 < 4; k16++) {
            unsigned a[2][2][4];
#pragma unroll
            for (int hf = 0; hf < 2; hf++)
#pragma unroll
                for (int mi = 0; mi < 2; mi++) {
                    int row = wm * 32 + mi * 16 + (l & 15);
                    ldsm4(a[hf][mi], stg + hf * 16384 + row * 128 +
                                     (((k16 * 2 + (l >> 4)) ^ (row & 7)) << 4));
                }
            unsigned b[2][8][2];
#pragma unroll
            for (int hf = 0; hf < 2; hf++)
#pragma unroll
                for (int cg = 0; cg < 4; cg++) {
                    int tileid = l >> 3;
                    int jr = (l & 7) + (tileid & 1) * 8;
                    int row = k16 * 16 + jr;
                    int seg = wn * 8 + cg * 2 + (tileid >> 1);
                    unsigned r4[4];
                    ldsm4t(r4, stg + 32768 + hf * 16384 + row * 256 +
                               ((seg ^ ((row & 7) << 1)) << 4));
                    b[hf][2 * cg][0] = r4[0]; b[hf][2 * cg][1] = r4[1];
                    b[hf][2 * cg + 1][0] = r4[2]; b[hf][2 * cg + 1][1] = r4[3];
                }
#pragma unroll
            for (int mi = 0; mi < 2; mi++)
#pragma unroll
                for (int nj = 0; nj < 8; nj++) {
                    mma16816(d[mi][nj], a[0][mi], b[0][nj]);
                    mma16816(d[mi][nj], a[0][mi], b[1][nj]);
                    mma16816(d[mi][nj], a[1][mi], b[0][nj]);
                }
        }
    }
    cp_wait0();
    __syncthreads();
    float* ep = (float*)dsm;
#pragma unroll
    for (int mi = 0; mi < 2; mi++)
#pragma unroll
        for (int nj = 0; nj < 8; nj++)
#pragma unroll
            for (int rg = 0; rg < 4; rg++) {
                int row = wm * 32 + mi * 16 + (l >> 2) + (rg >> 1) * 8;
                int col = wn * 64 + nj * 8 + (l & 3) * 2 + (rg & 1);
                ep[row * 129 + col] = d[mi][nj][rg];
            }
    __syncthreads();
    for (int r = wid; r < 128; r += 8) {
        float* dr = &g_virt[((size_t)p * NN + i0 + r) * CC + c0];
        for (int c = l; c < 128; c += 32) dr[c] = ep[r * 129 + c];
    }
}

// ---------------- GN stats ----------------
__global__ __launch_bounds__(256) void stats_kernel()
{
    __shared__ float r1[256];
    __shared__ float r2[256];
    const int n = blockIdx.x, tid = threadIdx.x;
    float s = 0.0f, s2 = 0.0f;
    for (int e = tid; e < PP * CC; e += 256) {
        int p = e >> 9, c = e & 511;
        float v = g_virt[(p * NN + n) * CC + c];
        s += v; s2 += v * v;
    }
    r1[tid] = s; r2[tid] = s2;
    __syncthreads();
    for (int off = 128; off; off >>= 1) {
        if (tid < off) { r1[tid] += r1[tid + off]; r2[tid] += r2[tid + off]; }
        __syncthreads();
    }
    if (tid == 0) {
        const float invN = 1.0f / (float)(PP * CC);
        float mu = r1[0] * invN;
        float var = r2[0] * invN - mu * mu;
        g_mu[n] = mu;
        g_rs[n] = rsqrtf(var + 1e-5f);
    }
}

// ---------------- host ----------------
extern "C" void kernel_launch(void* const* d_in, const int* in_sizes, int n_in,
                              void* d_out, int out_size)
{
    const float* x     = (const float*)d_in[0];
    const int*   roi   = (const int*)d_in[1];
    const float* Wq    = (const float*)d_in[2];
    const float* Wk    = (const float*)d_in[3];
    const float* Wv    = (const float*)d_in[4];
    const float* Wc    = (const float*)d_in[5];
    const float* gamma = (const float*)d_in[6];
    const float* beta  = (const float*)d_in[7];
    float* out = (float*)d_out;

    cudaFuncSetAttribute(conv_mma_kernel,   cudaFuncAttributeMaxDynamicSharedMemorySize, CONV_SMEM);
    cudaFuncSetAttribute(scores_mma_kernel, cudaFuncAttributeMaxDynamicSharedMemorySize, 3 * STG_SZ);
    cudaFuncSetAttribute(virt_mma_kernel,   cudaFuncAttributeMaxDynamicSharedMemorySize, 3 * STG_SZ);

    split_w_kernel<<<36864, 256>>>(Wq, Wk, Wv, Wc);
    split_x_kernel<<<dim3(4, 8, 256), 256>>>(x);
    conv_mma_kernel<<<dim3(4, 256, 3), 256, CONV_SMEM>>>(0, x, out);    // q,k,v
    scores_mma_kernel<<<dim3(4, 256), 256, 3 * STG_SZ>>>();
    softmax_kernel<<<8192, 256>>>(roi);
    virt_mma_kernel<<<dim3(8, 256), 256, 3 * STG_SZ>>>();
    stats_kernel<<<256, 256>>>();
    split_v_kernel<<<65536, 256>>>(gamma, beta);
    conv_mma_kernel<<<dim3(4, 256, 1), 256, CONV_SMEM>>>(3, x, out);    // out conv
}